// round 6
// baseline (speedup 1.0000x reference)
#include <cuda_runtime.h>
#include <cuda_bf16.h>
#include <cstdint>

// Problem constants
#define NN 8192
#define DD 256
#define KK 8
#define CC 1024          // NN / KK classes
#define MARGIN2 0.7f
#define NTILE 16         // 1024 / 64 tiles per dim
#define NBLK 136         // NTILE*(NTILE+1)/2 upper-triangular tiles

// Scratch (no allocations allowed)
__device__ __align__(16) __nv_bfloat16 g_cbf[CC * DD];  // bf16 class centers
__device__ float g_sq[CC];             // ||center||^2 (fp32 exact)
__device__ float g_dpc[CC];            // per-class sum of dist_pc
__device__ float g_an_part[NBLK];      // per-block hinge partial sums
__device__ unsigned int g_ctr;         // last-block counter (self-resetting)

__device__ __forceinline__ float dot4(const float4& a, const float4& b) {
    return a.x * b.x + a.y * b.y + a.z * b.z + a.w * b.w;
}
__device__ __forceinline__ float wreduce(float s) {
#pragma unroll
    for (int o = 16; o; o >>= 1) s += __shfl_xor_sync(0xFFFFFFFFu, s, o);
    return s;
}
__device__ __forceinline__ float4 f4_fma(const float4& a, float s, const float4& b) {
    return make_float4(fmaf(a.x, s, b.x), fmaf(a.y, s, b.y),
                       fmaf(a.z, s, b.z), fmaf(a.w, s, b.w));
}

// ---------------------------------------------------------------------------
// Kernel A: 4 warps per class, 2 rows per warp.  grid = 512 blocks x 256 thr.
// ---------------------------------------------------------------------------
__global__ __launch_bounds__(256) void centers_kernel(const float* __restrict__ x) {
    __shared__ float4 sm_part[2][4][64];   // [class][warp][lane f4]
    __shared__ float  sm_dpc[2][4];

    const int t    = threadIdx.x;
    const int lane = t & 31;
    const int wid  = t >> 5;
    const int cls  = wid >> 2;     // class within block
    const int wic  = wid & 3;      // warp within class
    const int c    = blockIdx.x * 2 + cls;

    const float4* p = reinterpret_cast<const float4*>(x + (size_t)c * KK * DD);

    float4 v[2][2];
#pragma unroll
    for (int r = 0; r < 2; r++) {
        const float4* rp = p + (2 * wic + r) * 64;
        v[r][0] = rp[lane];
        v[r][1] = rp[lane + 32];
    }

    float rn[2];
#pragma unroll
    for (int r = 0; r < 2; r++)
        rn[r] = rsqrtf(wreduce(dot4(v[r][0], v[r][0]) + dot4(v[r][1], v[r][1])));

    float4 z = make_float4(0.f, 0.f, 0.f, 0.f);
    float4 ps0 = f4_fma(v[1][0], rn[1], f4_fma(v[0][0], rn[0], z));
    float4 ps1 = f4_fma(v[1][1], rn[1], f4_fma(v[0][1], rn[0], z));
    sm_part[cls][wic][lane]      = ps0;
    sm_part[cls][wic][lane + 32] = ps1;
    __syncthreads();

    float4 c0 = sm_part[cls][0][lane];
    float4 c1 = sm_part[cls][0][lane + 32];
#pragma unroll
    for (int w = 1; w < 4; w++) {
        const float4 q0 = sm_part[cls][w][lane];
        const float4 q1 = sm_part[cls][w][lane + 32];
        c0.x += q0.x; c0.y += q0.y; c0.z += q0.z; c0.w += q0.w;
        c1.x += q1.x; c1.y += q1.y; c1.z += q1.z; c1.w += q1.w;
    }
    c0.x *= 0.125f; c0.y *= 0.125f; c0.z *= 0.125f; c0.w *= 0.125f;
    c1.x *= 0.125f; c1.y *= 0.125f; c1.z *= 0.125f; c1.w *= 0.125f;

    if (wic == 0) {
        __nv_bfloat162 p0 = __floats2bfloat162_rn(c0.x, c0.y);
        __nv_bfloat162 p1 = __floats2bfloat162_rn(c0.z, c0.w);
        __nv_bfloat162 p2 = __floats2bfloat162_rn(c1.x, c1.y);
        __nv_bfloat162 p3 = __floats2bfloat162_rn(c1.z, c1.w);
        uint2 u0, u1;
        u0.x = *reinterpret_cast<uint32_t*>(&p0); u0.y = *reinterpret_cast<uint32_t*>(&p1);
        u1.x = *reinterpret_cast<uint32_t*>(&p2); u1.y = *reinterpret_cast<uint32_t*>(&p3);
        *reinterpret_cast<uint2*>(&g_cbf[c * DD + 4 * lane]) = u0;
        *reinterpret_cast<uint2*>(&g_cbf[c * DD + 4 * lane + 128]) = u1;
    }

    const float s_sq = wreduce(dot4(c0, c0) + dot4(c1, c1));
    if (wic == 0 && lane == 0) g_sq[c] = s_sq;
    const float rcn = rsqrtf(s_sq);

    float dpc = 0.f;
#pragma unroll
    for (int r = 0; r < 2; r++) {
        float d;
        float t0 = fmaf(v[r][0].x, rn[r], -c0.x * rcn); d  = t0 * t0;
        float t1 = fmaf(v[r][0].y, rn[r], -c0.y * rcn); d += t1 * t1;
        float t2 = fmaf(v[r][0].z, rn[r], -c0.z * rcn); d += t2 * t2;
        float t3 = fmaf(v[r][0].w, rn[r], -c0.w * rcn); d += t3 * t3;
        float t4 = fmaf(v[r][1].x, rn[r], -c1.x * rcn); d += t4 * t4;
        float t5 = fmaf(v[r][1].y, rn[r], -c1.y * rcn); d += t5 * t5;
        float t6 = fmaf(v[r][1].z, rn[r], -c1.z * rcn); d += t6 * t6;
        float t7 = fmaf(v[r][1].w, rn[r], -c1.w * rcn); d += t7 * t7;
        dpc += sqrtf(wreduce(d));
    }
    if (lane == 0) sm_dpc[cls][wic] = dpc;
    __syncthreads();
    if (wic == 0 && lane == 0)
        g_dpc[c] = (sm_dpc[cls][0] + sm_dpc[cls][1]) + (sm_dpc[cls][2] + sm_dpc[cls][3]);
}

// ---------------------------------------------------------------------------
// Kernel B: symmetric pairwise hinge via bf16 mma.sync (m16n8k16).
// 64x64 upper-triangular tiles, 136 blocks, 512 threads (16 warps, 4x4 grid,
// 16x16 output per warp).  Register-prefetch double buffering over 2 K-stages.
// Last-arriving block performs the final global reduction.
// ---------------------------------------------------------------------------
#define BPAD 136   // bf16 row pitch: 272B stride, conflict-free for ldmatrix

__global__ __launch_bounds__(512) void pair_kernel(float* __restrict__ out) {
    __shared__ __nv_bfloat16 As[64][BPAD];
    __shared__ __nv_bfloat16 Bs[64][BPAD];
    __shared__ float warp_s[16];
    __shared__ unsigned int s_last;

    // decode upper-triangular tile index
    int rem = blockIdx.x, bi = 0;
    while (rem >= NTILE - bi) { rem -= NTILE - bi; bi++; }
    const int bj = bi + rem;
    const int rb = bi * 64, cb = bj * 64;

    const int t = threadIdx.x;
    const int lane = t & 31;
    const int wid = t >> 5;
    const int wr = wid >> 2;   // 0..3 -> 16-row slab
    const int wc = wid & 3;    // 0..3 -> 16-col slab

    float acc[2][4];
#pragma unroll
    for (int i = 0; i < 2; i++)
#pragma unroll
        for (int j = 0; j < 4; j++) acc[i][j] = 0.f;

    const uint4* gC = reinterpret_cast<const uint4*>(g_cbf);  // 8 bf16 / uint4

    // staging indices: 1024 uint4 per tile per stage, 2 per thread per tile
    const int r_0 = (t + 0)   >> 4, cu0 = (t + 0)   & 15;
    const int r_1 = (t + 512) >> 4, cu1 = (t + 512) & 15;

    uint4 pa0, pa1, pb0, pb1;
    // load stage 0
    pa0 = gC[((rb + r_0) * DD + 0) / 8 + cu0];
    pa1 = gC[((rb + r_1) * DD + 0) / 8 + cu1];
    pb0 = gC[((cb + r_0) * DD + 0) / 8 + cu0];
    pb1 = gC[((cb + r_1) * DD + 0) / 8 + cu1];
    *reinterpret_cast<uint4*>(&As[r_0][cu0 * 8]) = pa0;
    *reinterpret_cast<uint4*>(&As[r_1][cu1 * 8]) = pa1;
    *reinterpret_cast<uint4*>(&Bs[r_0][cu0 * 8]) = pb0;
    *reinterpret_cast<uint4*>(&Bs[r_1][cu1 * 8]) = pb1;
    __syncthreads();

    // prefetch stage 1 into registers (overlaps with stage-0 compute)
    pa0 = gC[((rb + r_0) * DD + 128) / 8 + cu0];
    pa1 = gC[((rb + r_1) * DD + 128) / 8 + cu1];
    pb0 = gC[((cb + r_0) * DD + 128) / 8 + cu0];
    pb1 = gC[((cb + r_1) * DD + 128) / 8 + cu1];

#pragma unroll
    for (int stage = 0; stage < 2; stage++) {
#pragma unroll
        for (int k0 = 0; k0 < 128; k0 += 16) {
            uint32_t a0, a1, a2, a3;
            {
                uint32_t aaddr = (uint32_t)__cvta_generic_to_shared(
                    &As[wr * 16 + (lane & 15)][k0 + ((lane >> 4) << 3)]);
                asm volatile(
                    "ldmatrix.sync.aligned.m8n8.x4.shared.b16 {%0,%1,%2,%3}, [%4];"
                    : "=r"(a0), "=r"(a1), "=r"(a2), "=r"(a3) : "r"(aaddr));
            }
            uint32_t b0, b1, b2, b3;
            {
                uint32_t baddr = (uint32_t)__cvta_generic_to_shared(
                    &Bs[wc * 16 + (lane & 7) + ((lane >> 4) & 1) * 8]
                       [k0 + ((lane >> 3) & 1) * 8]);
                asm volatile(
                    "ldmatrix.sync.aligned.m8n8.x4.shared.b16 {%0,%1,%2,%3}, [%4];"
                    : "=r"(b0), "=r"(b1), "=r"(b2), "=r"(b3) : "r"(baddr));
            }
            asm volatile(
                "mma.sync.aligned.m16n8k16.row.col.f32.bf16.bf16.f32 "
                "{%0,%1,%2,%3}, {%4,%5,%6,%7}, {%8,%9}, {%0,%1,%2,%3};"
                : "+f"(acc[0][0]), "+f"(acc[0][1]), "+f"(acc[0][2]), "+f"(acc[0][3])
                : "r"(a0), "r"(a1), "r"(a2), "r"(a3), "r"(b0), "r"(b1));
            asm volatile(
                "mma.sync.aligned.m16n8k16.row.col.f32.bf16.bf16.f32 "
                "{%0,%1,%2,%3}, {%4,%5,%6,%7}, {%8,%9}, {%0,%1,%2,%3};"
                : "+f"(acc[1][0]), "+f"(acc[1][1]), "+f"(acc[1][2]), "+f"(acc[1][3])
                : "r"(a0), "r"(a1), "r"(a2), "r"(a3), "r"(b2), "r"(b3));
        }
        if (stage == 0) {
            __syncthreads();   // all reads of stage-0 tiles done
            *reinterpret_cast<uint4*>(&As[r_0][cu0 * 8]) = pa0;
            *reinterpret_cast<uint4*>(&As[r_1][cu1 * 8]) = pa1;
            *reinterpret_cast<uint4*>(&Bs[r_0][cu0 * 8]) = pb0;
            *reinterpret_cast<uint4*>(&Bs[r_1][cu1 * 8]) = pb1;
            __syncthreads();
        }
    }

    // epilogue: hinge on each acc element
    // acc[g][0]=(r0,c0) [1]=(r0,c0+1) [2]=(r0+8,c0) [3]=(r0+8,c0+1), g: n-offset 8g
    const int r0 = rb + wr * 16 + (lane >> 2);
    const int r1 = r0 + 8;
    const float sqr0 = g_sq[r0];
    const float sqr1 = g_sq[r1];

    float s = 0.f;
#pragma unroll
    for (int g = 0; g < 2; g++) {
        const int c0 = cb + wc * 16 + g * 8 + 2 * (lane & 3);
        const float sc0 = g_sq[c0];
        const float sc1 = g_sq[c0 + 1];
        if (r0 != c0) {
            const float d2 = fmaxf(sqr0 + sc0 - 2.0f * acc[g][0], 1e-12f);
            s += fmaxf(MARGIN2 - sqrtf(d2), 0.0f);
        }
        if (r0 != c0 + 1) {
            const float d2 = fmaxf(sqr0 + sc1 - 2.0f * acc[g][1], 1e-12f);
            s += fmaxf(MARGIN2 - sqrtf(d2), 0.0f);
        }
        if (r1 != c0) {
            const float d2 = fmaxf(sqr1 + sc0 - 2.0f * acc[g][2], 1e-12f);
            s += fmaxf(MARGIN2 - sqrtf(d2), 0.0f);
        }
        if (r1 != c0 + 1) {
            const float d2 = fmaxf(sqr1 + sc1 - 2.0f * acc[g][3], 1e-12f);
            s += fmaxf(MARGIN2 - sqrtf(d2), 0.0f);
        }
    }
    if (bi != bj) s *= 2.0f;   // mirrored tile contributes identically

    s = wreduce(s);
    if (lane == 0) warp_s[wid] = s;
    __syncthreads();
    if (t == 0) {
        float tot = 0.f;
#pragma unroll
        for (int wv = 0; wv < 16; wv++) tot += warp_s[wv];
        g_an_part[blockIdx.x] = tot;
        __threadfence();
        s_last = (atomicAdd(&g_ctr, 1u) == NBLK - 1) ? 1u : 0u;
    }
    __syncthreads();

    // ---- last-arriving block: final deterministic reduction ----
    if (s_last) {
        __shared__ float sdw[16], saw[16];
        float d = __ldcg(&g_dpc[t]) + __ldcg(&g_dpc[t + 512]);
        float a = (t < NBLK) ? __ldcg(&g_an_part[t]) : 0.f;
        d = wreduce(d);
        a = wreduce(a);
        if (lane == 0) { sdw[wid] = d; saw[wid] = a; }
        __syncthreads();
        if (t == 0) {
            float D = 0.f, A = 0.f;
#pragma unroll
            for (int i = 0; i < 16; i++) { D += sdw[i]; A += saw[i]; }
            const float dpc_mean = D / (float)NN;
            const float an_mean  = A * (float)KK / ((float)(NN - KK) * (float)CC);
            out[0] = dpc_mean + an_mean;   // loss
            out[1] = dpc_mean;
            out[2] = an_mean;
            g_ctr = 0u;                    // reset for next graph replay
        }
    }
}

extern "C" void kernel_launch(void* const* d_in, const int* in_sizes, int n_in,
                              void* d_out, int out_size) {
    const float* x = (const float*)d_in[0];
    float* out = (float*)d_out;

    centers_kernel<<<CC / 2, 256>>>(x);
    pair_kernel<<<NBLK, 512>>>(out);
}